// round 9
// baseline (speedup 1.0000x reference)
#include <cuda_runtime.h>
#include <math.h>
#include <float.h>

typedef unsigned long long u64;

#define B_IMG  4
#define NPROP  2000
#define NSORT  2048
#define NGT    64
#define T_TOT  200
#define P_POS  66
#define NNEG   134
#define MH     28
#define MW     28
#define IMH    512
#define IMW    512
#define EPSF   1e-8f

#define OFF_ROIS   0
#define OFF_CLS    (B_IMG * T_TOT * 4)
#define OFF_DELTA  (OFF_CLS + B_IMG * T_TOT)
#define OFF_MASK   (OFF_DELTA + B_IMG * T_TOT * 4)

// Scratch (allocation-free rule: __device__ globals)
__device__ float         g_val[B_IMG][NPROP];
__device__ unsigned char g_bestg[B_IMG][NPROP];
__device__ float g_posbox[B_IMG][P_POS][4];
__device__ int   g_posassign[B_IMG][P_POS];
__device__ int   g_posvalid[B_IMG][P_POS];

__device__ __forceinline__ unsigned ordf(float f) {
    unsigned u = __float_as_uint(f);
    return (u & 0x80000000u) ? ~u : (u | 0x80000000u);
}

// ---------------------------------------------------------------------------
// Kernel 0: IoU max + argmax. (R7 measured-best config)
// grid = (B_IMG, 32), block = 256. Thread = (proposal, quarter of 16 GTs).
// ---------------------------------------------------------------------------
__global__ __launch_bounds__(256)
void iou_kernel(const float* __restrict__ props,
                const int*   __restrict__ gids,
                const float* __restrict__ gboxes)
{
    const int b   = blockIdx.x;
    const int tid = threadIdx.x;
    const int pl  = tid >> 2;            // proposal-slot in block
    const int q   = tid & 3;             // GT quarter
    const int i   = blockIdx.y * 64 + pl;

    __shared__ float s_gb[NGT][4];
    __shared__ float s_ga[NGT];
    __shared__ int   s_gid[NGT];

    if (tid < NGT) {
        const float4 qq = ((const float4*)gboxes)[(size_t)b * NGT + tid];
        s_gb[tid][0] = qq.x; s_gb[tid][1] = qq.y; s_gb[tid][2] = qq.z; s_gb[tid][3] = qq.w;
        s_ga[tid]    = __fmul_rn(__fsub_rn(qq.z, qq.x), __fsub_rn(qq.w, qq.y));
        s_gid[tid]   = gids[(size_t)b * NGT + tid];
    }
    __syncthreads();

    if (i >= NPROP) return;

    const float4 p = ((const float4*)props)[(size_t)b * NPROP + i];
    float p0 = p.x, p1 = p.y, p2 = p.z, p3 = p.w;
    float a1 = __fmul_rn(__fsub_rn(p2, p0), __fsub_rn(p3, p1));

    float best = -1.0f; int bj = q * 16;
    #pragma unroll
    for (int jj = 0; jj < 16; jj++) {
        int j = q * 16 + jj;
        float v;
        if (s_gid[j] > 0) {
            float yy1 = fmaxf(p0, s_gb[j][0]);
            float xx1 = fmaxf(p1, s_gb[j][1]);
            float yy2 = fminf(p2, s_gb[j][2]);
            float xx2 = fminf(p3, s_gb[j][3]);
            float ih  = fmaxf(__fsub_rn(yy2, yy1), 0.0f);
            float iw  = fmaxf(__fsub_rn(xx2, xx1), 0.0f);
            float inter = __fmul_rn(ih, iw);
            if (inter > 0.0f) {
                float un = __fsub_rn(__fadd_rn(a1, s_ga[j]), inter);
                v = __fdiv_rn(inter, fmaxf(un, EPSF));
            } else {
                v = 0.0f;                 // inter==0 -> IoU==0 exactly
            }
        } else {
            v = -1.0f;
        }
        if (v > best) { best = v; bj = j; }   // strict > => first max index
    }

    #pragma unroll
    for (int off = 1; off <= 2; off <<= 1) {
        float ov = __shfl_xor_sync(0xffffffffu, best, off);
        int   oj = __shfl_xor_sync(0xffffffffu, bj,   off);
        if (ov > best || (ov == best && oj < bj)) { best = ov; bj = oj; }
    }

    if (q == 0) {
        g_val[b][i]   = best;
        g_bestg[b][i] = (unsigned char)bj;
    }
}

// ---------------------------------------------------------------------------
// Hybrid bitonic sort of 2048 u64 keys, 1024 threads. (unchanged, proven)
// ---------------------------------------------------------------------------
__device__ __forceinline__ void bitonic2048(u64* __restrict__ s, int tid)
{
    #pragma unroll 1
    for (unsigned k = 2; k <= NSORT; k <<= 1) {
        #pragma unroll 1
        for (unsigned j = k >> 1; j >= 32; j >>= 1) {
            unsigned i = ((tid & ~(j - 1u)) << 1) | (tid & (j - 1u));
            unsigned p = i | j;
            bool up = ((i & k) == 0);
            u64 a = s[i], c = s[p];
            if ((a > c) == up) { s[i] = c; s[p] = a; }
            __syncthreads();
        }
        unsigned jstart = (k >> 1 < 32u) ? (k >> 1) : 16u;
        u64 r0 = s[tid], r1 = s[tid + 1024];
        bool up0 = ((unsigned)tid & k) == 0;
        bool up1 = (((unsigned)tid + 1024u) & k) == 0;
        #pragma unroll 1
        for (unsigned j = jstart; j >= 1; j >>= 1) {
            u64 o0 = __shfl_xor_sync(0xffffffffu, r0, j);
            bool lo = (((unsigned)tid & j) == 0);
            r0 = ((lo == up0) ? (r0 < o0) : (r0 > o0)) ? r0 : o0;
            u64 o1 = __shfl_xor_sync(0xffffffffu, r1, j);
            r1 = ((lo == up1) ? (r1 < o1) : (r1 > o1)) ? r1 : o1;
        }
        s[tid] = r0; s[tid + 1024] = r1;
        __syncthreads();
    }
}

// ---------------------------------------------------------------------------
// Kernel 1: selection. grid = 8 = (image, role). (unchanged)
// ---------------------------------------------------------------------------
__global__ __launch_bounds__(1024)
void select_kernel(const float* __restrict__ props,
                   const int*   __restrict__ gids,
                   const float* __restrict__ gboxes,
                   float*       __restrict__ out)
{
    const int b    = blockIdx.x >> 1;
    const int role = blockIdx.x & 1;
    const int tid  = threadIdx.x;

    __shared__ u64 s_sort[NSORT];
    __shared__ int s_idx[NNEG];
    __shared__ int s_poscnt;
    __shared__ int s_negn;

    if (tid == 0) s_poscnt = 0;
    __syncthreads();

    int my_posc = 0;
    #pragma unroll 1
    for (int i = tid; i < NSORT; i += 1024) {
        float key;
        if (i < NPROP) {
            float v = g_val[b][i];
            if (v >= 0.5f) my_posc++;
            key = (role == 0) ? (v >= 0.5f ? v : -1.0f)
                              : (v < 0.5f ? -v : -1000000000.0f);
        } else key = -FLT_MAX;
        s_sort[i] = ~((((u64)ordf(key)) << 32) | (unsigned)(~i));
    }
    my_posc += __shfl_xor_sync(0xffffffffu, my_posc, 16);
    my_posc += __shfl_xor_sync(0xffffffffu, my_posc, 8);
    my_posc += __shfl_xor_sync(0xffffffffu, my_posc, 4);
    my_posc += __shfl_xor_sync(0xffffffffu, my_posc, 2);
    my_posc += __shfl_xor_sync(0xffffffffu, my_posc, 1);
    if ((tid & 31) == 0 && my_posc) atomicAdd(&s_poscnt, my_posc);
    __syncthreads();

    bitonic2048(s_sort, tid);

    const int keep = (role == 0) ? P_POS : NNEG;
    if (tid < keep) s_idx[tid] = (int)(~(unsigned)(~s_sort[tid]));
    if (role == 1 && tid == 0) {
        int pc = min(s_poscnt, P_POS);
        int nt = (pc * 100) / 33 - pc;   // exact-rational floor, matches reference
        nt = min(max(nt, 0), NNEG);
        s_negn = min(nt, NPROP - s_poscnt);
    }
    __syncthreads();

    if (role == 0) {
        if (tid < P_POS) {
            const int k = tid;
            int idx = s_idx[k];
            float vv = g_val[b][idx];
            int valid = (vv >= 0.5f) ? 1 : 0;
            const float4 p = ((const float4*)props)[(size_t)b * NPROP + idx];
            float p0 = p.x, p1 = p.y, p2 = p.z, p3 = p.w;
            int a = (int)g_bestg[b][idx];

            g_posbox[b][k][0] = p0; g_posbox[b][k][1] = p1;
            g_posbox[b][k][2] = p2; g_posbox[b][k][3] = p3;
            g_posassign[b][k] = a;
            g_posvalid[b][k]  = valid;

            float r0=0.f,r1=0.f,r2=0.f,r3=0.f,d0=0.f,d1=0.f,d2=0.f,d3=0.f,clsf=0.f;
            if (valid) {
                r0 = p0; r1 = p1; r2 = p2; r3 = p3;
                clsf = (float)gids[(size_t)b * NGT + a];
                const float4 q = ((const float4*)gboxes)[(size_t)b * NGT + a];
                float h  = fmaxf(__fsub_rn(p2, p0), EPSF);
                float w  = fmaxf(__fsub_rn(p3, p1), EPSF);
                float cy = __fadd_rn(p0, __fmul_rn(0.5f, h));
                float cx = __fadd_rn(p1, __fmul_rn(0.5f, w));
                float gh  = fmaxf(__fsub_rn(q.z, q.x), EPSF);
                float gw  = fmaxf(__fsub_rn(q.w, q.y), EPSF);
                float gcy = __fadd_rn(q.x, __fmul_rn(0.5f, gh));
                float gcx = __fadd_rn(q.y, __fmul_rn(0.5f, gw));
                d0 = __fdiv_rn(__fdiv_rn(__fsub_rn(gcy, cy), h), 0.1f);
                d1 = __fdiv_rn(__fdiv_rn(__fsub_rn(gcx, cx), w), 0.1f);
                d2 = __fdiv_rn(logf(__fdiv_rn(gh, h)), 0.2f);
                d3 = __fdiv_rn(logf(__fdiv_rn(gw, w)), 0.2f);
            }
            size_t row = (size_t)b * T_TOT + k;
            out[OFF_ROIS  + row * 4 + 0] = r0;
            out[OFF_ROIS  + row * 4 + 1] = r1;
            out[OFF_ROIS  + row * 4 + 2] = r2;
            out[OFF_ROIS  + row * 4 + 3] = r3;
            out[OFF_CLS   + row]         = clsf;
            out[OFF_DELTA + row * 4 + 0] = d0;
            out[OFF_DELTA + row * 4 + 1] = d1;
            out[OFF_DELTA + row * 4 + 2] = d2;
            out[OFF_DELTA + row * 4 + 3] = d3;
        }
    } else {
        if (tid < NNEG) {
            const int kn = tid;
            float r0=0.f,r1=0.f,r2=0.f,r3=0.f;
            if (kn < s_negn) {
                int idx = s_idx[kn];
                const float4 p = ((const float4*)props)[(size_t)b * NPROP + idx];
                r0 = p.x; r1 = p.y; r2 = p.z; r3 = p.w;
            }
            size_t row = (size_t)b * T_TOT + P_POS + kn;
            out[OFF_ROIS  + row * 4 + 0] = r0;
            out[OFF_ROIS  + row * 4 + 1] = r1;
            out[OFF_ROIS  + row * 4 + 2] = r2;
            out[OFF_ROIS  + row * 4 + 3] = r3;
            out[OFF_CLS   + row]         = 0.0f;
            out[OFF_DELTA + row * 4 + 0] = 0.0f;
            out[OFF_DELTA + row * 4 + 1] = 0.0f;
            out[OFF_DELTA + row * 4 + 2] = 0.0f;
            out[OFF_DELTA + row * 4 + 3] = 0.0f;
        }
    }
}

// ---------------------------------------------------------------------------
// Kernel 2: mask crops. grid = 800, block = 256, 3-4 px/thread with ALL
// addresses computed first and 12-16 independent loads in flight (MLP 12+).
// ---------------------------------------------------------------------------
__global__ __launch_bounds__(256)
void mask_kernel(const float* __restrict__ masks_in,
                 float*       __restrict__ out)
{
    const int blk = blockIdx.x;
    const int b   = blk / T_TOT;
    const int k   = blk - b * T_TOT;
    const int tid = threadIdx.x;

    float* mout = out + OFF_MASK + ((size_t)b * T_TOT + k) * (MH * MW);

    bool valid = (k < P_POS) && (g_posvalid[b][k] != 0);
    if (!valid) {
        // 784 px = 196 float4
        if (tid < 196) ((float4*)mout)[tid] = make_float4(0.f, 0.f, 0.f, 0.f);
        return;
    }

    const int a = g_posassign[b][k];
    const float by1 = g_posbox[b][k][0];
    const float bx1 = g_posbox[b][k][1];
    const float dy  = __fsub_rn(g_posbox[b][k][2], by1);
    const float dx  = __fsub_rn(g_posbox[b][k][3], bx1);

    // s=0..2 always valid (tid+512 <= 767 < 784); s=3 only for tid < 16.
    const int NS = 4;
    float wy[NS], wx[NS];
    const float* addr00[NS]; const float* addr01[NS];
    const float* addr10[NS]; const float* addr11[NS];
    int npx = (tid < 16) ? 4 : 3;

    #pragma unroll
    for (int s = 0; s < NS; s++) {
        int p = tid + (s << 8);
        if (s >= npx) p = 0;             // clamp; result discarded
        int i = p / MW;
        int j = p - i * MW;

        // Python precedence: (y1 + ((y2-y1)*i)/(MH-1)) * (H-1)
        float fy = __fdiv_rn(__fmul_rn(dy, (float)i), (float)(MH - 1));
        float ys = __fmul_rn(__fadd_rn(by1, fy), (float)(IMH - 1));
        float y0f = floorf(ys);
        wy[s] = __fsub_rn(ys, y0f);
        int y0 = (int)fminf(fmaxf(y0f, 0.0f), (float)(IMH - 1));
        int y1 = (int)fminf(fmaxf(__fadd_rn(y0f, 1.0f), 0.0f), (float)(IMH - 1));

        float fx = __fdiv_rn(__fmul_rn(dx, (float)j), (float)(MW - 1));
        float xs = __fmul_rn(__fadd_rn(bx1, fx), (float)(IMW - 1));
        float x0f = floorf(xs);
        wx[s] = __fsub_rn(xs, x0f);
        int x0 = (int)fminf(fmaxf(x0f, 0.0f), (float)(IMW - 1));
        int x1 = (int)fminf(fmaxf(__fadd_rn(x0f, 1.0f), 0.0f), (float)(IMW - 1));

        size_t base = (size_t)b * IMH;
        addr00[s] = masks_in + ((base + y0) * IMW + x0) * NGT + a;
        addr01[s] = masks_in + ((base + y0) * IMW + x1) * NGT + a;
        addr10[s] = masks_in + ((base + y1) * IMW + x0) * NGT + a;
        addr11[s] = masks_in + ((base + y1) * IMW + x1) * NGT + a;
    }

    // issue all loads back-to-back (independent -> deep MLP)
    float v00[NS], v01[NS], v10[NS], v11[NS];
    #pragma unroll
    for (int s = 0; s < NS; s++) {
        v00[s] = __ldg(addr00[s]);
        v01[s] = __ldg(addr01[s]);
        v10[s] = __ldg(addr10[s]);
        v11[s] = __ldg(addr11[s]);
    }

    #pragma unroll
    for (int s = 0; s < NS; s++) {
        if (s >= npx) break;
        float omx = __fsub_rn(1.0f, wx[s]);
        float omy = __fsub_rn(1.0f, wy[s]);
        float top = __fadd_rn(__fmul_rn(v00[s], omx), __fmul_rn(v01[s], wx[s]));
        float bot = __fadd_rn(__fmul_rn(v10[s], omx), __fmul_rn(v11[s], wx[s]));
        float val = __fadd_rn(__fmul_rn(top, omy), __fmul_rn(bot, wy[s]));
        mout[tid + (s << 8)] = rintf(val);   // half-to-even, matches jnp.round
    }
}

// ---------------------------------------------------------------------------
extern "C" void kernel_launch(void* const* d_in, const int* in_sizes, int n_in,
                              void* d_out, int out_size)
{
    const float* props    = nullptr;
    const int*   gids     = nullptr;
    const float* gboxes   = nullptr;
    const float* masks_in = nullptr;
    for (int i = 0; i < n_in; i++) {
        switch (in_sizes[i]) {
            case B_IMG * NPROP * 4: props  = (const float*)d_in[i]; break;
            case B_IMG * NGT:       gids   = (const int*)  d_in[i]; break;
            case B_IMG * NGT * 4:   gboxes = (const float*)d_in[i]; break;
            default:
                if (in_sizes[i] == B_IMG * IMH * IMW * NGT)
                    masks_in = (const float*)d_in[i];
                break;
        }
    }
    if (!props)    props    = (const float*)d_in[0];
    if (!gids)     gids     = (const int*)  d_in[1];
    if (!gboxes)   gboxes   = (const float*)d_in[2];
    if (!masks_in) masks_in = (const float*)d_in[3];

    float* out = (float*)d_out;

    iou_kernel<<<dim3(B_IMG, 32), 256>>>(props, gids, gboxes);
    select_kernel<<<B_IMG * 2, 1024>>>(props, gids, gboxes, out);
    mask_kernel<<<B_IMG * T_TOT, 256>>>(masks_in, out);
}

// round 10
// speedup vs baseline: 1.0615x; 1.0615x over previous
#include <cuda_runtime.h>
#include <math.h>
#include <float.h>

typedef unsigned long long u64;

#define B_IMG  4
#define NPROP  2000
#define NSORT  2048
#define NGT    64
#define T_TOT  200
#define P_POS  66
#define NNEG   134
#define MH     28
#define MW     28
#define IMH    512
#define IMW    512
#define EPSF   1e-8f

#define OFF_ROIS   0
#define OFF_CLS    (B_IMG * T_TOT * 4)
#define OFF_DELTA  (OFF_CLS + B_IMG * T_TOT)
#define OFF_MASK   (OFF_DELTA + B_IMG * T_TOT * 4)

// Scratch (allocation-free rule: __device__ globals)
__device__ float         g_val[B_IMG][NPROP];
__device__ unsigned char g_bestg[B_IMG][NPROP];
__device__ float g_posbox[B_IMG][P_POS][4];
__device__ int   g_posassign[B_IMG][P_POS];
__device__ int   g_posvalid[B_IMG][P_POS];

__device__ __forceinline__ unsigned ordf(float f) {
    unsigned u = __float_as_uint(f);
    return (u & 0x80000000u) ? ~u : (u | 0x80000000u);
}

// ---------------------------------------------------------------------------
// Kernel 0: IoU max + argmax. grid = (B_IMG, 32), block = 256.
// Thread = (proposal, quarter of 16 GTs). Props prefetched before barrier.
// ---------------------------------------------------------------------------
__global__ __launch_bounds__(256)
void iou_kernel(const float* __restrict__ props,
                const int*   __restrict__ gids,
                const float* __restrict__ gboxes)
{
    const int b   = blockIdx.x;
    const int tid = threadIdx.x;
    const int pl  = tid >> 2;            // proposal-slot in block
    const int q   = tid & 3;             // GT quarter
    const int i   = blockIdx.y * 64 + pl;

    __shared__ float s_gb[NGT][4];
    __shared__ float s_ga[NGT];
    __shared__ int   s_gid[NGT];

    // prefetch proposal BEFORE the barrier so its DRAM trip overlaps the
    // gbox smem fill instead of serializing behind it
    const bool act = (i < NPROP);
    float4 p = make_float4(0.f, 0.f, 0.f, 0.f);
    if (act) p = ((const float4*)props)[(size_t)b * NPROP + i];

    if (tid < NGT) {
        const float4 qq = ((const float4*)gboxes)[(size_t)b * NGT + tid];
        s_gb[tid][0] = qq.x; s_gb[tid][1] = qq.y; s_gb[tid][2] = qq.z; s_gb[tid][3] = qq.w;
        s_ga[tid]    = __fmul_rn(__fsub_rn(qq.z, qq.x), __fsub_rn(qq.w, qq.y));
        s_gid[tid]   = gids[(size_t)b * NGT + tid];
    }
    __syncthreads();

    if (!act) return;

    float p0 = p.x, p1 = p.y, p2 = p.z, p3 = p.w;
    float a1 = __fmul_rn(__fsub_rn(p2, p0), __fsub_rn(p3, p1));

    float best = -1.0f; int bj = q * 16;
    #pragma unroll
    for (int jj = 0; jj < 16; jj++) {
        int j = q * 16 + jj;
        float v;
        if (s_gid[j] > 0) {
            float yy1 = fmaxf(p0, s_gb[j][0]);
            float xx1 = fmaxf(p1, s_gb[j][1]);
            float yy2 = fminf(p2, s_gb[j][2]);
            float xx2 = fminf(p3, s_gb[j][3]);
            float ih  = fmaxf(__fsub_rn(yy2, yy1), 0.0f);
            float iw  = fmaxf(__fsub_rn(xx2, xx1), 0.0f);
            float inter = __fmul_rn(ih, iw);
            if (inter > 0.0f) {
                float un = __fsub_rn(__fadd_rn(a1, s_ga[j]), inter);
                v = __fdiv_rn(inter, fmaxf(un, EPSF));
            } else {
                v = 0.0f;                 // inter==0 -> IoU==0 exactly
            }
        } else {
            v = -1.0f;
        }
        if (v > best) { best = v; bj = j; }   // strict > => first max index
    }

    #pragma unroll
    for (int off = 1; off <= 2; off <<= 1) {
        float ov = __shfl_xor_sync(0xffffffffu, best, off);
        int   oj = __shfl_xor_sync(0xffffffffu, bj,   off);
        if (ov > best || (ov == best && oj < bj)) { best = ov; bj = oj; }
    }

    if (q == 0) {
        g_val[b][i]   = best;
        g_bestg[b][i] = (unsigned char)bj;
    }
}

// ---------------------------------------------------------------------------
// Hybrid bitonic sort of 2048 u64 keys, 1024 threads. (unchanged, proven)
// ---------------------------------------------------------------------------
__device__ __forceinline__ void bitonic2048(u64* __restrict__ s, int tid)
{
    #pragma unroll 1
    for (unsigned k = 2; k <= NSORT; k <<= 1) {
        #pragma unroll 1
        for (unsigned j = k >> 1; j >= 32; j >>= 1) {
            unsigned i = ((tid & ~(j - 1u)) << 1) | (tid & (j - 1u));
            unsigned p = i | j;
            bool up = ((i & k) == 0);
            u64 a = s[i], c = s[p];
            if ((a > c) == up) { s[i] = c; s[p] = a; }
            __syncthreads();
        }
        unsigned jstart = (k >> 1 < 32u) ? (k >> 1) : 16u;
        u64 r0 = s[tid], r1 = s[tid + 1024];
        bool up0 = ((unsigned)tid & k) == 0;
        bool up1 = (((unsigned)tid + 1024u) & k) == 0;
        #pragma unroll 1
        for (unsigned j = jstart; j >= 1; j >>= 1) {
            u64 o0 = __shfl_xor_sync(0xffffffffu, r0, j);
            bool lo = (((unsigned)tid & j) == 0);
            r0 = ((lo == up0) ? (r0 < o0) : (r0 > o0)) ? r0 : o0;
            u64 o1 = __shfl_xor_sync(0xffffffffu, r1, j);
            r1 = ((lo == up1) ? (r1 < o1) : (r1 > o1)) ? r1 : o1;
        }
        s[tid] = r0; s[tid + 1024] = r1;
        __syncthreads();
    }
}

// ---------------------------------------------------------------------------
// Kernel 1: selection. grid = 8 = (image, role). (unchanged)
// ---------------------------------------------------------------------------
__global__ __launch_bounds__(1024)
void select_kernel(const float* __restrict__ props,
                   const int*   __restrict__ gids,
                   const float* __restrict__ gboxes,
                   float*       __restrict__ out)
{
    const int b    = blockIdx.x >> 1;
    const int role = blockIdx.x & 1;
    const int tid  = threadIdx.x;

    __shared__ u64 s_sort[NSORT];
    __shared__ int s_idx[NNEG];
    __shared__ int s_poscnt;
    __shared__ int s_negn;

    if (tid == 0) s_poscnt = 0;
    __syncthreads();

    int my_posc = 0;
    #pragma unroll 1
    for (int i = tid; i < NSORT; i += 1024) {
        float key;
        if (i < NPROP) {
            float v = g_val[b][i];
            if (v >= 0.5f) my_posc++;
            key = (role == 0) ? (v >= 0.5f ? v : -1.0f)
                              : (v < 0.5f ? -v : -1000000000.0f);
        } else key = -FLT_MAX;
        s_sort[i] = ~((((u64)ordf(key)) << 32) | (unsigned)(~i));
    }
    my_posc += __shfl_xor_sync(0xffffffffu, my_posc, 16);
    my_posc += __shfl_xor_sync(0xffffffffu, my_posc, 8);
    my_posc += __shfl_xor_sync(0xffffffffu, my_posc, 4);
    my_posc += __shfl_xor_sync(0xffffffffu, my_posc, 2);
    my_posc += __shfl_xor_sync(0xffffffffu, my_posc, 1);
    if ((tid & 31) == 0 && my_posc) atomicAdd(&s_poscnt, my_posc);
    __syncthreads();

    bitonic2048(s_sort, tid);

    const int keep = (role == 0) ? P_POS : NNEG;
    if (tid < keep) s_idx[tid] = (int)(~(unsigned)(~s_sort[tid]));
    if (role == 1 && tid == 0) {
        int pc = min(s_poscnt, P_POS);
        int nt = (pc * 100) / 33 - pc;   // exact-rational floor, matches reference
        nt = min(max(nt, 0), NNEG);
        s_negn = min(nt, NPROP - s_poscnt);
    }
    __syncthreads();

    if (role == 0) {
        if (tid < P_POS) {
            const int k = tid;
            int idx = s_idx[k];
            float vv = g_val[b][idx];
            int valid = (vv >= 0.5f) ? 1 : 0;
            const float4 p = ((const float4*)props)[(size_t)b * NPROP + idx];
            float p0 = p.x, p1 = p.y, p2 = p.z, p3 = p.w;
            int a = (int)g_bestg[b][idx];

            g_posbox[b][k][0] = p0; g_posbox[b][k][1] = p1;
            g_posbox[b][k][2] = p2; g_posbox[b][k][3] = p3;
            g_posassign[b][k] = a;
            g_posvalid[b][k]  = valid;

            float r0=0.f,r1=0.f,r2=0.f,r3=0.f,d0=0.f,d1=0.f,d2=0.f,d3=0.f,clsf=0.f;
            if (valid) {
                r0 = p0; r1 = p1; r2 = p2; r3 = p3;
                clsf = (float)gids[(size_t)b * NGT + a];
                const float4 q = ((const float4*)gboxes)[(size_t)b * NGT + a];
                float h  = fmaxf(__fsub_rn(p2, p0), EPSF);
                float w  = fmaxf(__fsub_rn(p3, p1), EPSF);
                float cy = __fadd_rn(p0, __fmul_rn(0.5f, h));
                float cx = __fadd_rn(p1, __fmul_rn(0.5f, w));
                float gh  = fmaxf(__fsub_rn(q.z, q.x), EPSF);
                float gw  = fmaxf(__fsub_rn(q.w, q.y), EPSF);
                float gcy = __fadd_rn(q.x, __fmul_rn(0.5f, gh));
                float gcx = __fadd_rn(q.y, __fmul_rn(0.5f, gw));
                d0 = __fdiv_rn(__fdiv_rn(__fsub_rn(gcy, cy), h), 0.1f);
                d1 = __fdiv_rn(__fdiv_rn(__fsub_rn(gcx, cx), w), 0.1f);
                d2 = __fdiv_rn(logf(__fdiv_rn(gh, h)), 0.2f);
                d3 = __fdiv_rn(logf(__fdiv_rn(gw, w)), 0.2f);
            }
            size_t row = (size_t)b * T_TOT + k;
            out[OFF_ROIS  + row * 4 + 0] = r0;
            out[OFF_ROIS  + row * 4 + 1] = r1;
            out[OFF_ROIS  + row * 4 + 2] = r2;
            out[OFF_ROIS  + row * 4 + 3] = r3;
            out[OFF_CLS   + row]         = clsf;
            out[OFF_DELTA + row * 4 + 0] = d0;
            out[OFF_DELTA + row * 4 + 1] = d1;
            out[OFF_DELTA + row * 4 + 2] = d2;
            out[OFF_DELTA + row * 4 + 3] = d3;
        }
    } else {
        if (tid < NNEG) {
            const int kn = tid;
            float r0=0.f,r1=0.f,r2=0.f,r3=0.f;
            if (kn < s_negn) {
                int idx = s_idx[kn];
                const float4 p = ((const float4*)props)[(size_t)b * NPROP + idx];
                r0 = p.x; r1 = p.y; r2 = p.z; r3 = p.w;
            }
            size_t row = (size_t)b * T_TOT + P_POS + kn;
            out[OFF_ROIS  + row * 4 + 0] = r0;
            out[OFF_ROIS  + row * 4 + 1] = r1;
            out[OFF_ROIS  + row * 4 + 2] = r2;
            out[OFF_ROIS  + row * 4 + 3] = r3;
            out[OFF_CLS   + row]         = 0.0f;
            out[OFF_DELTA + row * 4 + 0] = 0.0f;
            out[OFF_DELTA + row * 4 + 1] = 0.0f;
            out[OFF_DELTA + row * 4 + 2] = 0.0f;
            out[OFF_DELTA + row * 4 + 3] = 0.0f;
        }
    }
}

// ---------------------------------------------------------------------------
// Kernel 2: mask crops. grid = (B*T, 7), block = 128 (R7 measured-best shape)
// + smem interpolation tables: 56 IEEE divs per block instead of 256.
// ---------------------------------------------------------------------------
__global__ __launch_bounds__(128)
void mask_kernel(const float* __restrict__ masks_in,
                 float*       __restrict__ out)
{
    const int blk = blockIdx.x;
    const int b   = blk / T_TOT;
    const int k   = blk - b * T_TOT;
    const int tid = threadIdx.x;
    const int p   = blockIdx.y * 128 + tid;

    float* mout = out + OFF_MASK + ((size_t)b * T_TOT + k) * (MH * MW);

    bool valid = (k < P_POS) && (g_posvalid[b][k] != 0);
    if (!valid) {
        // zero-fill this block's 128-px slice via float4 (32 per block; last
        // slice covers only 16 px = 4 float4s, guarded by the 196 limit)
        int f = blockIdx.y * 32 + tid;
        if (tid < 32 && f < 196)
            ((float4*)mout)[f] = make_float4(0.f, 0.f, 0.f, 0.f);
        return;
    }

    __shared__ float s_wy[MH], s_wx[MW];
    __shared__ int   s_y0[MH], s_y1[MH], s_x0[MW], s_x1[MW];

    const float by1 = g_posbox[b][k][0];
    const float bx1 = g_posbox[b][k][1];
    const float dy  = __fsub_rn(g_posbox[b][k][2], by1);
    const float dx  = __fsub_rn(g_posbox[b][k][3], bx1);

    // Python precedence: (y1 + ((y2-y1)*i)/(MH-1)) * (H-1)
    if (tid < MH) {
        int i = tid;
        float fy = __fdiv_rn(__fmul_rn(dy, (float)i), (float)(MH - 1));
        float ys = __fmul_rn(__fadd_rn(by1, fy), (float)(IMH - 1));
        float y0f = floorf(ys);
        s_wy[i] = __fsub_rn(ys, y0f);
        s_y0[i] = (int)fminf(fmaxf(y0f, 0.0f), (float)(IMH - 1));
        s_y1[i] = (int)fminf(fmaxf(__fadd_rn(y0f, 1.0f), 0.0f), (float)(IMH - 1));
    } else if (tid >= 32 && tid < 32 + MW) {
        int j = tid - 32;
        float fx = __fdiv_rn(__fmul_rn(dx, (float)j), (float)(MW - 1));
        float xs = __fmul_rn(__fadd_rn(bx1, fx), (float)(IMW - 1));
        float x0f = floorf(xs);
        s_wx[j] = __fsub_rn(xs, x0f);
        s_x0[j] = (int)fminf(fmaxf(x0f, 0.0f), (float)(IMW - 1));
        s_x1[j] = (int)fminf(fmaxf(__fadd_rn(x0f, 1.0f), 0.0f), (float)(IMW - 1));
    }
    __syncthreads();

    if (p >= MH * MW) return;

    const int a = g_posassign[b][k];
    int i = p / MW;
    int j = p - i * MW;
    int y0 = s_y0[i], y1 = s_y1[i];
    int x0 = s_x0[j], x1 = s_x1[j];
    float wy = s_wy[i], wx = s_wx[j];

    size_t base = (size_t)b * IMH;
    float v00 = __ldg(masks_in + ((base + y0) * IMW + x0) * NGT + a);
    float v01 = __ldg(masks_in + ((base + y0) * IMW + x1) * NGT + a);
    float v10 = __ldg(masks_in + ((base + y1) * IMW + x0) * NGT + a);
    float v11 = __ldg(masks_in + ((base + y1) * IMW + x1) * NGT + a);

    float omx = __fsub_rn(1.0f, wx);
    float omy = __fsub_rn(1.0f, wy);
    float top = __fadd_rn(__fmul_rn(v00, omx), __fmul_rn(v01, wx));
    float bot = __fadd_rn(__fmul_rn(v10, omx), __fmul_rn(v11, wx));
    float val = __fadd_rn(__fmul_rn(top, omy), __fmul_rn(bot, wy));
    mout[p] = rintf(val);   // half-to-even, matches jnp.round
}

// ---------------------------------------------------------------------------
extern "C" void kernel_launch(void* const* d_in, const int* in_sizes, int n_in,
                              void* d_out, int out_size)
{
    const float* props    = nullptr;
    const int*   gids     = nullptr;
    const float* gboxes   = nullptr;
    const float* masks_in = nullptr;
    for (int i = 0; i < n_in; i++) {
        switch (in_sizes[i]) {
            case B_IMG * NPROP * 4: props  = (const float*)d_in[i]; break;
            case B_IMG * NGT:       gids   = (const int*)  d_in[i]; break;
            case B_IMG * NGT * 4:   gboxes = (const float*)d_in[i]; break;
            default:
                if (in_sizes[i] == B_IMG * IMH * IMW * NGT)
                    masks_in = (const float*)d_in[i];
                break;
        }
    }
    if (!props)    props    = (const float*)d_in[0];
    if (!gids)     gids     = (const int*)  d_in[1];
    if (!gboxes)   gboxes   = (const float*)d_in[2];
    if (!masks_in) masks_in = (const float*)d_in[3];

    float* out = (float*)d_out;

    iou_kernel<<<dim3(B_IMG, 32), 256>>>(props, gids, gboxes);
    select_kernel<<<B_IMG * 2, 1024>>>(props, gids, gboxes, out);
    mask_kernel<<<dim3(B_IMG * T_TOT, 7), 128>>>(masks_in, out);
}

// round 12
// speedup vs baseline: 1.1182x; 1.0534x over previous
#include <cuda_runtime.h>
#include <math.h>
#include <float.h>

typedef unsigned long long u64;

#define B_IMG  4
#define NPROP  2000
#define NSORT  2048
#define NGT    64
#define T_TOT  200
#define P_POS  66
#define NNEG   134
#define MH     28
#define MW     28
#define IMH    512
#define IMW    512
#define EPSF   1e-8f

#define OFF_ROIS   0
#define OFF_CLS    (B_IMG * T_TOT * 4)
#define OFF_DELTA  (OFF_CLS + B_IMG * T_TOT)
#define OFF_MASK   (OFF_DELTA + B_IMG * T_TOT * 4)
#define MASK_F4    ((B_IMG * T_TOT * MH * MW) / 4)   // 156800 float4s

// Scratch (allocation-free rule: __device__ globals)
__device__ float         g_val[B_IMG][NPROP];
__device__ unsigned char g_bestg[B_IMG][NPROP];
__device__ float g_posbox[B_IMG][P_POS][4];
__device__ int   g_posassign[B_IMG][P_POS];
__device__ int   g_posvalid[B_IMG][P_POS];

__device__ __forceinline__ unsigned ordf(float f) {
    unsigned u = __float_as_uint(f);
    return (u & 0x80000000u) ? ~u : (u | 0x80000000u);
}

// ---------------------------------------------------------------------------
// Kernel 0: IoU max + argmax + mask-region zero-fill (dependency-free work
// moved off the critical path). grid = (B_IMG, 32), block = 256.
// ---------------------------------------------------------------------------
__global__ __launch_bounds__(256)
void iou_kernel(const float* __restrict__ props,
                const int*   __restrict__ gids,
                const float* __restrict__ gboxes,
                float*       __restrict__ out)
{
    const int b   = blockIdx.x;
    const int tid = threadIdx.x;
    const int pl  = tid >> 2;            // proposal-slot in block
    const int q   = tid & 3;             // GT quarter
    const int i   = blockIdx.y * 64 + pl;

    __shared__ float s_gb[NGT][4];
    __shared__ float s_ga[NGT];
    __shared__ int   s_gid[NGT];

    // prefetch proposal BEFORE the barrier (overlaps gbox smem fill)
    const bool act = (i < NPROP);
    float4 p = make_float4(0.f, 0.f, 0.f, 0.f);
    if (act) p = ((const float4*)props)[(size_t)b * NPROP + i];

    // zero-fill the entire mask output region (fire-and-forget stores;
    // 32768 threads x <=5 float4 each). Gather kernel later overwrites
    // only the valid positive rows.
    {
        float4* m4 = (float4*)(out + OFF_MASK);
        int gid = ((b << 5) + blockIdx.y) * 256 + tid;   // 0..32767
        #pragma unroll
        for (int s = 0; s < 5; s++) {
            int f = gid + s * 32768;
            if (f < MASK_F4) m4[f] = make_float4(0.f, 0.f, 0.f, 0.f);
        }
    }

    if (tid < NGT) {
        const float4 qq = ((const float4*)gboxes)[(size_t)b * NGT + tid];
        s_gb[tid][0] = qq.x; s_gb[tid][1] = qq.y; s_gb[tid][2] = qq.z; s_gb[tid][3] = qq.w;
        s_ga[tid]    = __fmul_rn(__fsub_rn(qq.z, qq.x), __fsub_rn(qq.w, qq.y));
        s_gid[tid]   = gids[(size_t)b * NGT + tid];
    }
    __syncthreads();

    if (!act) return;

    float p0 = p.x, p1 = p.y, p2 = p.z, p3 = p.w;
    float a1 = __fmul_rn(__fsub_rn(p2, p0), __fsub_rn(p3, p1));

    float best = -1.0f; int bj = q * 16;
    #pragma unroll
    for (int jj = 0; jj < 16; jj++) {
        int j = q * 16 + jj;
        float v;
        if (s_gid[j] > 0) {
            float yy1 = fmaxf(p0, s_gb[j][0]);
            float xx1 = fmaxf(p1, s_gb[j][1]);
            float yy2 = fminf(p2, s_gb[j][2]);
            float xx2 = fminf(p3, s_gb[j][3]);
            float ih  = fmaxf(__fsub_rn(yy2, yy1), 0.0f);
            float iw  = fmaxf(__fsub_rn(xx2, xx1), 0.0f);
            float inter = __fmul_rn(ih, iw);
            if (inter > 0.0f) {
                float un = __fsub_rn(__fadd_rn(a1, s_ga[j]), inter);
                v = __fdiv_rn(inter, fmaxf(un, EPSF));
            } else {
                v = 0.0f;                 // inter==0 -> IoU==0 exactly
            }
        } else {
            v = -1.0f;
        }
        if (v > best) { best = v; bj = j; }   // strict > => first max index
    }

    #pragma unroll
    for (int off = 1; off <= 2; off <<= 1) {
        float ov = __shfl_xor_sync(0xffffffffu, best, off);
        int   oj = __shfl_xor_sync(0xffffffffu, bj,   off);
        if (ov > best || (ov == best && oj < bj)) { best = ov; bj = oj; }
    }

    if (q == 0) {
        g_val[b][i]   = best;
        g_bestg[b][i] = (unsigned char)bj;
    }
}

// ---------------------------------------------------------------------------
// Hybrid bitonic sort of 2048 u64 keys, 1024 threads. (unchanged, proven)
// ---------------------------------------------------------------------------
__device__ __forceinline__ void bitonic2048(u64* __restrict__ s, int tid)
{
    #pragma unroll 1
    for (unsigned k = 2; k <= NSORT; k <<= 1) {
        #pragma unroll 1
        for (unsigned j = k >> 1; j >= 32; j >>= 1) {
            unsigned i = ((tid & ~(j - 1u)) << 1) | (tid & (j - 1u));
            unsigned p = i | j;
            bool up = ((i & k) == 0);
            u64 a = s[i], c = s[p];
            if ((a > c) == up) { s[i] = c; s[p] = a; }
            __syncthreads();
        }
        unsigned jstart = (k >> 1 < 32u) ? (k >> 1) : 16u;
        u64 r0 = s[tid], r1 = s[tid + 1024];
        bool up0 = ((unsigned)tid & k) == 0;
        bool up1 = (((unsigned)tid + 1024u) & k) == 0;
        #pragma unroll 1
        for (unsigned j = jstart; j >= 1; j >>= 1) {
            u64 o0 = __shfl_xor_sync(0xffffffffu, r0, j);
            bool lo = (((unsigned)tid & j) == 0);
            r0 = ((lo == up0) ? (r0 < o0) : (r0 > o0)) ? r0 : o0;
            u64 o1 = __shfl_xor_sync(0xffffffffu, r1, j);
            r1 = ((lo == up1) ? (r1 < o1) : (r1 > o1)) ? r1 : o1;
        }
        s[tid] = r0; s[tid + 1024] = r1;
        __syncthreads();
    }
}

// ---------------------------------------------------------------------------
// Kernel 1: selection. grid = 8 = (image, role). (unchanged, proven)
// ---------------------------------------------------------------------------
__global__ __launch_bounds__(1024)
void select_kernel(const float* __restrict__ props,
                   const int*   __restrict__ gids,
                   const float* __restrict__ gboxes,
                   float*       __restrict__ out)
{
    const int b    = blockIdx.x >> 1;
    const int role = blockIdx.x & 1;
    const int tid  = threadIdx.x;

    __shared__ u64 s_sort[NSORT];
    __shared__ int s_idx[NNEG];
    __shared__ int s_poscnt;
    __shared__ int s_negn;

    if (tid == 0) s_poscnt = 0;
    __syncthreads();

    int my_posc = 0;
    #pragma unroll 1
    for (int i = tid; i < NSORT; i += 1024) {
        float key;
        if (i < NPROP) {
            float v = g_val[b][i];
            if (v >= 0.5f) my_posc++;
            key = (role == 0) ? (v >= 0.5f ? v : -1.0f)
                              : (v < 0.5f ? -v : -1000000000.0f);
        } else key = -FLT_MAX;
        s_sort[i] = ~((((u64)ordf(key)) << 32) | (unsigned)(~i));
    }
    my_posc += __shfl_xor_sync(0xffffffffu, my_posc, 16);
    my_posc += __shfl_xor_sync(0xffffffffu, my_posc, 8);
    my_posc += __shfl_xor_sync(0xffffffffu, my_posc, 4);
    my_posc += __shfl_xor_sync(0xffffffffu, my_posc, 2);
    my_posc += __shfl_xor_sync(0xffffffffu, my_posc, 1);
    if ((tid & 31) == 0 && my_posc) atomicAdd(&s_poscnt, my_posc);
    __syncthreads();

    bitonic2048(s_sort, tid);

    const int keep = (role == 0) ? P_POS : NNEG;
    if (tid < keep) s_idx[tid] = (int)(~(unsigned)(~s_sort[tid]));
    if (role == 1 && tid == 0) {
        int pc = min(s_poscnt, P_POS);
        int nt = (pc * 100) / 33 - pc;   // exact-rational floor, matches reference
        nt = min(max(nt, 0), NNEG);
        s_negn = min(nt, NPROP - s_poscnt);
    }
    __syncthreads();

    if (role == 0) {
        if (tid < P_POS) {
            const int k = tid;
            int idx = s_idx[k];
            float vv = g_val[b][idx];
            int valid = (vv >= 0.5f) ? 1 : 0;
            const float4 p = ((const float4*)props)[(size_t)b * NPROP + idx];
            float p0 = p.x, p1 = p.y, p2 = p.z, p3 = p.w;
            int a = (int)g_bestg[b][idx];

            g_posbox[b][k][0] = p0; g_posbox[b][k][1] = p1;
            g_posbox[b][k][2] = p2; g_posbox[b][k][3] = p3;
            g_posassign[b][k] = a;
            g_posvalid[b][k]  = valid;

            float r0=0.f,r1=0.f,r2=0.f,r3=0.f,d0=0.f,d1=0.f,d2=0.f,d3=0.f,clsf=0.f;
            if (valid) {
                r0 = p0; r1 = p1; r2 = p2; r3 = p3;
                clsf = (float)gids[(size_t)b * NGT + a];
                const float4 q = ((const float4*)gboxes)[(size_t)b * NGT + a];
                float h  = fmaxf(__fsub_rn(p2, p0), EPSF);
                float w  = fmaxf(__fsub_rn(p3, p1), EPSF);
                float cy = __fadd_rn(p0, __fmul_rn(0.5f, h));
                float cx = __fadd_rn(p1, __fmul_rn(0.5f, w));
                float gh  = fmaxf(__fsub_rn(q.z, q.x), EPSF);
                float gw  = fmaxf(__fsub_rn(q.w, q.y), EPSF);
                float gcy = __fadd_rn(q.x, __fmul_rn(0.5f, gh));
                float gcx = __fadd_rn(q.y, __fmul_rn(0.5f, gw));
                d0 = __fdiv_rn(__fdiv_rn(__fsub_rn(gcy, cy), h), 0.1f);
                d1 = __fdiv_rn(__fdiv_rn(__fsub_rn(gcx, cx), w), 0.1f);
                d2 = __fdiv_rn(logf(__fdiv_rn(gh, h)), 0.2f);
                d3 = __fdiv_rn(logf(__fdiv_rn(gw, w)), 0.2f);
            }
            size_t row = (size_t)b * T_TOT + k;
            out[OFF_ROIS  + row * 4 + 0] = r0;
            out[OFF_ROIS  + row * 4 + 1] = r1;
            out[OFF_ROIS  + row * 4 + 2] = r2;
            out[OFF_ROIS  + row * 4 + 3] = r3;
            out[OFF_CLS   + row]         = clsf;
            out[OFF_DELTA + row * 4 + 0] = d0;
            out[OFF_DELTA + row * 4 + 1] = d1;
            out[OFF_DELTA + row * 4 + 2] = d2;
            out[OFF_DELTA + row * 4 + 3] = d3;
        }
    } else {
        if (tid < NNEG) {
            const int kn = tid;
            float r0=0.f,r1=0.f,r2=0.f,r3=0.f;
            if (kn < s_negn) {
                int idx = s_idx[kn];
                const float4 p = ((const float4*)props)[(size_t)b * NPROP + idx];
                r0 = p.x; r1 = p.y; r2 = p.z; r3 = p.w;
            }
            size_t row = (size_t)b * T_TOT + P_POS + kn;
            out[OFF_ROIS  + row * 4 + 0] = r0;
            out[OFF_ROIS  + row * 4 + 1] = r1;
            out[OFF_ROIS  + row * 4 + 2] = r2;
            out[OFF_ROIS  + row * 4 + 3] = r3;
            out[OFF_CLS   + row]         = 0.0f;
            out[OFF_DELTA + row * 4 + 0] = 0.0f;
            out[OFF_DELTA + row * 4 + 1] = 0.0f;
            out[OFF_DELTA + row * 4 + 2] = 0.0f;
            out[OFF_DELTA + row * 4 + 3] = 0.0f;
        }
    }
}

// ---------------------------------------------------------------------------
// Kernel 2: mask gather. grid = (B*P_POS, 7), block = 128 — pos rows only;
// the whole mask region was pre-zeroed in iou_kernel, so invalid rows skip.
// ---------------------------------------------------------------------------
__global__ __launch_bounds__(128)
void mask_kernel(const float* __restrict__ masks_in,
                 float*       __restrict__ out)
{
    const int blk = blockIdx.x;
    const int b   = blk / P_POS;
    const int k   = blk - b * P_POS;          // pos row 0..65
    const int tid = threadIdx.x;
    const int p   = blockIdx.y * 128 + tid;

    if (g_posvalid[b][k] == 0) return;        // region already zeroed

    float* mout = out + OFF_MASK + ((size_t)b * T_TOT + k) * (MH * MW);

    __shared__ float s_wy[MH], s_wx[MW];
    __shared__ int   s_y0[MH], s_y1[MH], s_x0[MW], s_x1[MW];

    const float by1 = g_posbox[b][k][0];
    const float bx1 = g_posbox[b][k][1];
    const float dy  = __fsub_rn(g_posbox[b][k][2], by1);
    const float dx  = __fsub_rn(g_posbox[b][k][3], bx1);

    // Python precedence: (y1 + ((y2-y1)*i)/(MH-1)) * (H-1)
    if (tid < MH) {
        int i = tid;
        float fy = __fdiv_rn(__fmul_rn(dy, (float)i), (float)(MH - 1));
        float ys = __fmul_rn(__fadd_rn(by1, fy), (float)(IMH - 1));
        float y0f = floorf(ys);
        s_wy[i] = __fsub_rn(ys, y0f);
        s_y0[i] = (int)fminf(fmaxf(y0f, 0.0f), (float)(IMH - 1));
        s_y1[i] = (int)fminf(fmaxf(__fadd_rn(y0f, 1.0f), 0.0f), (float)(IMH - 1));
    } else if (tid >= 32 && tid < 32 + MW) {
        int j = tid - 32;
        float fx = __fdiv_rn(__fmul_rn(dx, (float)j), (float)(MW - 1));
        float xs = __fmul_rn(__fadd_rn(bx1, fx), (float)(IMW - 1));
        float x0f = floorf(xs);
        s_wx[j] = __fsub_rn(xs, x0f);
        s_x0[j] = (int)fminf(fmaxf(x0f, 0.0f), (float)(IMW - 1));
        s_x1[j] = (int)fminf(fmaxf(__fadd_rn(x0f, 1.0f), 0.0f), (float)(IMW - 1));
    }
    __syncthreads();

    if (p >= MH * MW) return;

    const int a = g_posassign[b][k];
    int i = p / MW;
    int j = p - i * MW;
    int y0 = s_y0[i], y1 = s_y1[i];
    int x0 = s_x0[j], x1 = s_x1[j];
    float wy = s_wy[i], wx = s_wx[j];

    size_t base = (size_t)b * IMH;
    float v00 = __ldg(masks_in + ((base + y0) * IMW + x0) * NGT + a);
    float v01 = __ldg(masks_in + ((base + y0) * IMW + x1) * NGT + a);
    float v10 = __ldg(masks_in + ((base + y1) * IMW + x0) * NGT + a);
    float v11 = __ldg(masks_in + ((base + y1) * IMW + x1) * NGT + a);

    float omx = __fsub_rn(1.0f, wx);
    float omy = __fsub_rn(1.0f, wy);
    float top = __fadd_rn(__fmul_rn(v00, omx), __fmul_rn(v01, wx));
    float bot = __fadd_rn(__fmul_rn(v10, omx), __fmul_rn(v11, wx));
    float val = __fadd_rn(__fmul_rn(top, omy), __fmul_rn(bot, wy));
    mout[p] = rintf(val);   // half-to-even, matches jnp.round
}

// ---------------------------------------------------------------------------
extern "C" void kernel_launch(void* const* d_in, const int* in_sizes, int n_in,
                              void* d_out, int out_size)
{
    const float* props    = nullptr;
    const int*   gids     = nullptr;
    const float* gboxes   = nullptr;
    const float* masks_in = nullptr;
    for (int i = 0; i < n_in; i++) {
        switch (in_sizes[i]) {
            case B_IMG * NPROP * 4: props  = (const float*)d_in[i]; break;
            case B_IMG * NGT:       gids   = (const int*)  d_in[i]; break;
            case B_IMG * NGT * 4:   gboxes = (const float*)d_in[i]; break;
            default:
                if (in_sizes[i] == B_IMG * IMH * IMW * NGT)
                    masks_in = (const float*)d_in[i];
                break;
        }
    }
    if (!props)    props    = (const float*)d_in[0];
    if (!gids)     gids     = (const int*)  d_in[1];
    if (!gboxes)   gboxes   = (const float*)d_in[2];
    if (!masks_in) masks_in = (const float*)d_in[3];

    float* out = (float*)d_out;

    iou_kernel<<<dim3(B_IMG, 32), 256>>>(props, gids, gboxes, out);
    select_kernel<<<B_IMG * 2, 1024>>>(props, gids, gboxes, out);
    mask_kernel<<<dim3(B_IMG * P_POS, 7), 128>>>(masks_in, out);
}